// round 14
// baseline (speedup 1.0000x reference)
#include <cuda_runtime.h>
#include <cuda_bf16.h>
#include <cstdint>

#define EPS_ 1e-5f

// ---------------- scratch (single __device__ array) ----------------
__device__ float g_scratch[27885824];

__device__ __forceinline__ float warp_sum(float v) {
#pragma unroll
    for (int o = 16; o; o >>= 1) v += __shfl_down_sync(0xffffffffu, v, o);
    return v;
}

// split fp32 -> (hi bf16, lo bf16) pairs packed as bf16x2 words
__device__ __forceinline__ void cvt_split(float a, float b, uint32_t& hi, uint32_t& lo) {
    __nv_bfloat162 h = __floats2bfloat162_rn(a, b);
    float2 hf = __bfloat1622float2(h);
    __nv_bfloat162 l = __floats2bfloat162_rn(a - hf.x, b - hf.y);
    hi = *reinterpret_cast<uint32_t*>(&h);
    lo = *reinterpret_cast<uint32_t*>(&l);
}

__device__ __forceinline__ void mma16816(float* c, const uint32_t* a, const uint32_t* b) {
    asm volatile(
        "mma.sync.aligned.m16n8k16.row.col.f32.bf16.bf16.f32 "
        "{%0,%1,%2,%3}, {%4,%5,%6,%7}, {%8,%9}, {%0,%1,%2,%3};"
        : "+f"(c[0]), "+f"(c[1]), "+f"(c[2]), "+f"(c[3])
        : "r"(a[0]), "r"(a[1]), "r"(a[2]), "r"(a[3]), "r"(b[0]), "r"(b[1]));
}

__device__ __forceinline__ void ldsm4(uint32_t* r, uint32_t addr) {
    asm volatile(
        "ldmatrix.sync.aligned.m8n8.x4.shared.b16 {%0,%1,%2,%3}, [%4];"
        : "=r"(r[0]), "=r"(r[1]), "=r"(r[2]), "=r"(r[3]) : "r"(addr));
}

// ===========================================================================
// mma.sync GEMM, K-chunk 32, 2-stage smem double buffer + register prefetch.
// Quad-region smem layout + ldmatrix fragment loads (R9/R10/R13 structure).
// ARED: A operand is a split-K partial sum: A = act(Abias[col] + sum_sp plane_sp)
//   ARED=1: 4 planes, no relu. ARED=2: 2 planes + relu. (fused spreduce)
// STATS (with BCONV,EPI=3): block-reduce sum/sumsq of outputs -> psum/psq slot.
// C[m,n] = act( sum_k A[m,k]*B[n,k] (+bias) (+res) )
// Block 256 thr (8 warps, 4x2 of 32x32 warp tiles), tile M=128 x N=64,
// split-K = blockIdx.z. SHIFT: v_next row remap. BCONV: 1x1-conv B gather.
// EPI: 0=partial store (split-K), 1=bias, 2=bias+relu, 3=bias+residual.
// ===========================================================================
#define AQ0 0
#define AQ1 520
#define AQ2 1040
#define AQ3 1560
#define APLANE 2080          // A low plane base (word offset)
#define BQ0 0
#define BQ1 264
#define BQ2 528
#define BQ3 792
#define BH_BASE 4160
#define BL_BASE 5216
#define BUF_WORDS 6272
#define BUF_BYTES 25088
#define MG_SMEM (2 * BUF_BYTES)   // 50176 B -> dynamic smem, opt-in >48KB

template <int SHIFT, int BCONV, int EPI, int ARED, int STATS>
__global__ __launch_bounds__(256, 2) void mg_kernel(
    const float* __restrict__ A, const float* __restrict__ Bm,
    const float* __restrict__ bias, const float* __restrict__ res,
    float* __restrict__ C, const float* __restrict__ Abias,
    float* __restrict__ psum, float* __restrict__ psq,
    int K, int kLen, int Ntot, int Astride, int aplane)
{
    extern __shared__ __align__(128) uint32_t SM[];
    const int t = threadIdx.x, w = t >> 5, lid = t & 31;
    const int wm = (w >> 1) * 32, wn = (w & 1) * 32;
    const int t4 = lid & 3, grp = lid >> 2;
    const int n0 = blockIdx.x * 64;
    const int m0 = blockIdx.y * 128;
    const int sp = blockIdx.z;
    const int k0base = sp * kLen;
    const int nn = n0 >> 8, p0 = n0 & 255;  // BCONV decode

    float acc[2][4][4];
#pragma unroll
    for (int i = 0; i < 2; i++)
#pragma unroll
        for (int j = 0; j < 4; j++)
#pragma unroll
            for (int q = 0; q < 4; q++) acc[i][j][q] = 0.f;

    // ---- A global-load mapping: row = t>>1, 16 consecutive k at (t&1)*16 ----
    int am = m0 + (t >> 1);
    if (SHIFT) { int bb = am >> 5, ii = (am & 31) + 1; if (ii > 31) ii = 31; am = (bb << 5) + ii; }
    const float* Aptr = A + (size_t)am * Astride + k0base + (t & 1) * 16;
    const float* Abp = ARED ? (Abias + k0base + (t & 1) * 16) : nullptr;
    const int ar4 = (t >> 1) * 4;
    const int ah_ = t & 1;
    const int iA0 = (ah_ ? AQ2 : AQ0) + ar4;
    const int iA1 = (ah_ ? AQ3 : AQ1) + ar4;

    // ---- B global-load mapping (threads 0..127) ----
    const int bactive = (t < 128);
    const int brow = BCONV ? (t & 63) : (t >> 1);
    const int bh_ = BCONV ? ((t >> 6) & 1) : (t & 1);
    const float* Bptr = BCONV
        ? Bm + (size_t)nn * 65536 + (size_t)(bh_ * 16) * 256 + p0 + brow
        : Bm + (size_t)(n0 + brow) * K + k0base + bh_ * 16;
    const int br4 = brow * 4;
    const int iB0 = BH_BASE + (bh_ ? BQ2 : BQ0) + br4;
    const int iB1 = BH_BASE + (bh_ ? BQ3 : BQ1) + br4;

    // ---- ldmatrix lane-address bases (bytes into buffer 0) ----
    const uint32_t smb = (uint32_t)__cvta_generic_to_shared(SM);
    const uint32_t baseA = smb + 4u * ((lid < 16 ? AQ0 : AQ1) + (uint32_t)(wm + (lid & 15)) * 4u);
    const uint32_t baseB = smb + 4u * ((uint32_t)BH_BASE + (((lid >> 3) & 1) ? BQ1 : BQ0)
                                       + (uint32_t)(wn + ((lid >> 4) << 3) + (lid & 7)) * 4u);

    const int nchunks = kLen >> 5;
    float apf[16], bpf[16];

#define MG_LOADA(KC)                                                         \
    if (!ARED) {                                                             \
        const float* p_ = Aptr + (KC);                                       \
        _Pragma("unroll")                                                    \
        for (int i = 0; i < 16; i += 4) {                                    \
            float4 v = *(const float4*)(p_ + i);                             \
            apf[i] = v.x; apf[i+1] = v.y; apf[i+2] = v.z; apf[i+3] = v.w;    \
        }                                                                    \
    } else {                                                                 \
        const int NSP_ = (ARED == 1) ? 4 : 2;                                \
        _Pragma("unroll")                                                    \
        for (int i = 0; i < 16; i += 4) {                                    \
            float4 s_ = *(const float4*)(Abp + (KC) + i);                    \
            for (int sp_ = 0; sp_ < NSP_; sp_++) {                           \
                float4 v = *(const float4*)(Aptr + (size_t)sp_ * aplane + (KC) + i); \
                s_.x += v.x; s_.y += v.y; s_.z += v.z; s_.w += v.w;          \
            }                                                                \
            if (ARED == 2) {                                                 \
                s_.x = fmaxf(s_.x, 0.f); s_.y = fmaxf(s_.y, 0.f);            \
                s_.z = fmaxf(s_.z, 0.f); s_.w = fmaxf(s_.w, 0.f);            \
            }                                                                \
            apf[i] = s_.x; apf[i+1] = s_.y; apf[i+2] = s_.z; apf[i+3] = s_.w;\
        }                                                                    \
    }

#define MG_LOADB(KC)                                                         \
    if (bactive) {                                                           \
        if (!BCONV) {                                                        \
            const float* q_ = Bptr + (KC);                                   \
            _Pragma("unroll")                                                \
            for (int i = 0; i < 16; i += 4) {                                \
                float4 v = *(const float4*)(q_ + i);                         \
                bpf[i] = v.x; bpf[i+1] = v.y; bpf[i+2] = v.z; bpf[i+3] = v.w;\
            }                                                                \
        } else {                                                             \
            const float* q_ = Bptr + (size_t)(KC) * 256;                     \
            _Pragma("unroll")                                                \
            for (int i = 0; i < 16; i++) bpf[i] = q_[i * 256];               \
        }                                                                    \
    }

#define MG_STORE(BW)                                                         \
    {                                                                        \
        uint32_t hw[8], lw[8];                                               \
        _Pragma("unroll")                                                    \
        for (int i = 0; i < 16; i += 4) {                                    \
            cvt_split(apf[i], apf[i+1], hw[i/2], lw[i/2]);                   \
            cvt_split(apf[i+2], apf[i+3], hw[i/2+1], lw[i/2+1]);             \
        }                                                                    \
        *(uint4*)(SM + (BW) + iA0)          = make_uint4(hw[0], hw[1], hw[2], hw[3]); \
        *(uint4*)(SM + (BW) + iA1)          = make_uint4(hw[4], hw[5], hw[6], hw[7]); \
        *(uint4*)(SM + (BW) + iA0 + APLANE) = make_uint4(lw[0], lw[1], lw[2], lw[3]); \
        *(uint4*)(SM + (BW) + iA1 + APLANE) = make_uint4(lw[4], lw[5], lw[6], lw[7]); \
        if (bactive) {                                                       \
            uint32_t bh2[8], bl2[8];                                         \
            _Pragma("unroll")                                                \
            for (int i = 0; i < 16; i += 4) {                                \
                cvt_split(bpf[i], bpf[i+1], bh2[i/2], bl2[i/2]);             \
                cvt_split(bpf[i+2], bpf[i+3], bh2[i/2+1], bl2[i/2+1]);       \
            }                                                                \
            *(uint4*)(SM + (BW) + iB0)                       = make_uint4(bh2[0], bh2[1], bh2[2], bh2[3]); \
            *(uint4*)(SM + (BW) + iB1)                       = make_uint4(bh2[4], bh2[5], bh2[6], bh2[7]); \
            *(uint4*)(SM + (BW) + iB0 + (BL_BASE - BH_BASE)) = make_uint4(bl2[0], bl2[1], bl2[2], bl2[3]); \
            *(uint4*)(SM + (BW) + iB1 + (BL_BASE - BH_BASE)) = make_uint4(bl2[4], bl2[5], bl2[6], bl2[7]); \
        }                                                                    \
    }

    // ---- prologue: chunk 0 -> buf0; chunk 1 -> regs ----
    MG_LOADA(0)
    MG_LOADB(0)
    MG_STORE(0)
    if (nchunks > 1) {
        MG_LOADA(32)
        MG_LOADB(32)
    }

    for (int ch = 0; ch < nchunks; ch++) {
        __syncthreads();
        if (ch + 1 < nchunks) {
            const int bw = ((ch + 1) & 1) * BUF_WORDS;
            MG_STORE(bw)
        }
        if (ch + 2 < nchunks) {
            const int kc = (ch + 2) << 5;
            MG_LOADA(kc)
            MG_LOADB(kc)
        }
        // ---- compute chunk ch from buf[ch&1] ----
        const uint32_t bufb = (uint32_t)(ch & 1) * BUF_BYTES;
#pragma unroll
        for (int ks = 0; ks < 2; ks++) {
            const uint32_t aksoff = bufb + (uint32_t)ks * 4160u;
            const uint32_t bksoff = bufb + (uint32_t)ks * 2112u;
            uint32_t ah0[4], ah1[4], al0[4], al1[4], b0[4], b1[4];
            ldsm4(ah0, baseA + aksoff);
            ldsm4(ah1, baseA + aksoff + 256u);
            ldsm4(b0, baseB + bksoff);
            ldsm4(b1, baseB + bksoff + 256u);
            mma16816(acc[0][0], ah0, b0);     mma16816(acc[0][1], ah0, b0 + 2);
            mma16816(acc[0][2], ah0, b1);     mma16816(acc[0][3], ah0, b1 + 2);
            mma16816(acc[1][0], ah1, b0);     mma16816(acc[1][1], ah1, b0 + 2);
            mma16816(acc[1][2], ah1, b1);     mma16816(acc[1][3], ah1, b1 + 2);
            ldsm4(al0, baseA + aksoff + 8320u);
            ldsm4(al1, baseA + aksoff + 8320u + 256u);
            mma16816(acc[0][0], al0, b0);     mma16816(acc[0][1], al0, b0 + 2);
            mma16816(acc[0][2], al0, b1);     mma16816(acc[0][3], al0, b1 + 2);
            mma16816(acc[1][0], al1, b0);     mma16816(acc[1][1], al1, b0 + 2);
            mma16816(acc[1][2], al1, b1);     mma16816(acc[1][3], al1, b1 + 2);
            ldsm4(b0, baseB + bksoff + 4224u);
            ldsm4(b1, baseB + bksoff + 4224u + 256u);
            mma16816(acc[0][0], ah0, b0);     mma16816(acc[0][1], ah0, b0 + 2);
            mma16816(acc[0][2], ah0, b1);     mma16816(acc[0][3], ah0, b1 + 2);
            mma16816(acc[1][0], ah1, b0);     mma16816(acc[1][1], ah1, b0 + 2);
            mma16816(acc[1][2], ah1, b1);     mma16816(acc[1][3], ah1, b1 + 2);
        }
    }
#undef MG_LOADA
#undef MG_LOADB
#undef MG_STORE

    // ---- epilogue ----
    float ls = 0.f, lq = 0.f;  // STATS accumulators
#pragma unroll
    for (int mi = 0; mi < 2; mi++) {
        const int r0 = m0 + wm + mi * 16 + grp;
        const int r1 = r0 + 8;
        if (EPI == 0) {
            float* C0 = C + ((size_t)sp * 128 + r0) * Ntot + n0;
            float* C1 = C + ((size_t)sp * 128 + r1) * Ntot + n0;
#pragma unroll
            for (int ni = 0; ni < 4; ni++) {
                const int cw = wn + ni * 8 + 2 * t4;
                *(float2*)(C0 + cw) = make_float2(acc[mi][ni][0], acc[mi][ni][1]);
                *(float2*)(C1 + cw) = make_float2(acc[mi][ni][2], acc[mi][ni][3]);
            }
        } else if (!BCONV) {
            float* C0 = C + (size_t)r0 * Ntot;
            float* C1 = C + (size_t)r1 * Ntot;
#pragma unroll
            for (int ni = 0; ni < 4; ni++) {
                const int col = n0 + wn + ni * 8 + 2 * t4;
                float b0_ = bias[col], b1_ = bias[col + 1];
                float2 o0 = make_float2(acc[mi][ni][0] + b0_, acc[mi][ni][1] + b1_);
                float2 o1 = make_float2(acc[mi][ni][2] + b0_, acc[mi][ni][3] + b1_);
                if (EPI == 2) {
                    o0.x = fmaxf(o0.x, 0.f); o0.y = fmaxf(o0.y, 0.f);
                    o1.x = fmaxf(o1.x, 0.f); o1.y = fmaxf(o1.y, 0.f);
                }
                *(float2*)(C0 + col) = o0;
                *(float2*)(C1 + col) = o1;
            }
        } else {
            const float bm0 = bias[r0], bm1 = bias[r1];
            float* P0 = C + (size_t)nn * 65536 + (size_t)r0 * 256 + p0;
            float* P1 = C + (size_t)nn * 65536 + (size_t)r1 * 256 + p0;
            const float* R0 = (EPI == 3) ? res + (size_t)nn * 65536 + (size_t)r0 * 256 + p0 : nullptr;
            const float* R1 = (EPI == 3) ? res + (size_t)nn * 65536 + (size_t)r1 * 256 + p0 : nullptr;
#pragma unroll
            for (int ni = 0; ni < 4; ni++) {
                const int cw = wn + ni * 8 + 2 * t4;
                float2 o0 = make_float2(acc[mi][ni][0] + bm0, acc[mi][ni][1] + bm0);
                float2 o1 = make_float2(acc[mi][ni][2] + bm1, acc[mi][ni][3] + bm1);
                if (EPI == 2) {
                    o0.x = fmaxf(o0.x, 0.f); o0.y = fmaxf(o0.y, 0.f);
                    o1.x = fmaxf(o1.x, 0.f); o1.y = fmaxf(o1.y, 0.f);
                }
                if (EPI == 3) {
                    float2 q0 = *(const float2*)(R0 + cw);
                    float2 q1 = *(const float2*)(R1 + cw);
                    o0.x += q0.x; o0.y += q0.y; o1.x += q1.x; o1.y += q1.y;
                }
                if (STATS) {
                    ls += o0.x + o0.y + o1.x + o1.y;
                    lq += o0.x * o0.x + o0.y * o0.y + o1.x * o1.x + o1.y * o1.y;
                }
                *(float2*)(P0 + cw) = o0;
                *(float2*)(P1 + cw) = o1;
            }
        }
    }

    if (STATS) {
        __syncthreads();   // SM free after this (compute loop done for all warps)
        float* red = (float*)SM;
        ls = warp_sum(ls);
        lq = warp_sum(lq);
        if (lid == 0) { red[w] = ls; red[8 + w] = lq; }
        __syncthreads();
        if (t == 0) {
            float S = 0.f, Q = 0.f;
            for (int i = 0; i < 8; i++) { S += red[i]; Q += red[8 + i]; }
            const int slot = ((n0 >> 6) & 3) | ((int)blockIdx.y << 2);
            psum[nn * 8 + slot] = S;
            psq[nn * 8 + slot] = Q;
        }
    }
}

// ===================== split-K reduce, float4 (+bias) =====================
template <int RELU>
__global__ __launch_bounds__(256) void spreduce_kernel(
    const float* __restrict__ ws, const float* __restrict__ bias,
    float* __restrict__ out, int nsp, int Nel, int NtotMask)
{
    int idx = (blockIdx.x * 256 + threadIdx.x) * 4;
    if (idx >= Nel) return;
    float4 s = *(const float4*)&bias[idx & NtotMask];
    for (int sp = 0; sp < nsp; sp++) {
        float4 v = *(const float4*)&ws[(size_t)sp * Nel + idx];
        s.x += v.x; s.y += v.y; s.z += v.z; s.w += v.w;
    }
    if (RELU) {
        s.x = fmaxf(s.x, 0.f); s.y = fmaxf(s.y, 0.f);
        s.z = fmaxf(s.z, 0.f); s.w = fmaxf(s.w, 0.f);
    }
    *(float4*)&out[idx] = s;
}

// ===================== SIMT kernels (mem-bound) =====================
// ln1 fused with attn split-K reduce: attn = bo + sum_sp planes; x = attn + tp
__global__ __launch_bounds__(512) void ln1f_kernel(
    const float* __restrict__ planes, const float* __restrict__ bo,
    const float* __restrict__ tp,
    const float* __restrict__ g, const float* __restrict__ b, float* __restrict__ enh)
{
    int m = blockIdx.x, t = threadIdx.x;
    int idx = m * 512 + t;
    float a = bo[t];
#pragma unroll
    for (int sp = 0; sp < 4; sp++) a += planes[sp * 65536 + idx];
    float x = a + tp[idx];
    __shared__ float sS[16], sQ[16];
    __shared__ float mu_s, rs_s;
    float s = warp_sum(x), q = warp_sum(x * x);
    int wid = t >> 5, lane = t & 31;
    if (lane == 0) { sS[wid] = s; sQ[wid] = q; }
    __syncthreads();
    if (t == 0) {
        float S = 0, Q = 0;
        for (int i = 0; i < 16; i++) { S += sS[i]; Q += sQ[i]; }
        float mu = S * (1.f / 512.f);
        float var = Q * (1.f / 512.f) - mu * mu;
        mu_s = mu; rs_s = rsqrtf(var + EPS_);
    }
    __syncthreads();
    enh[idx] = (x - mu_s) * rs_s * g[t] + b[t];
}

__global__ __launch_bounds__(256) void gap_kernel(
    const float* __restrict__ fa, float* __restrict__ gap)
{
    int m = blockIdx.x, t = threadIdx.x;
    int wid = t >> 5, lane = t & 31;
    for (int it = 0; it < 32; it++) {
        int c = wid * 32 + it;
        const float* p = fa + (size_t)m * 65536 + c * 256 + lane * 8;
        float4 a = *(const float4*)p;
        float4 b = *(const float4*)(p + 4);
        float s = a.x + a.y + a.z + a.w + b.x + b.y + b.z + b.w;
        s = warp_sum(s);
        if (lane == 0) gap[m * 256 + c] = s * (1.f / 256.f);
    }
}

__global__ __launch_bounds__(256) void dw_kernel(
    const float* __restrict__ fa, const float* __restrict__ kern, float* __restrict__ out)
{
    int c = blockIdx.x, m = blockIdx.y, t = threadIdx.x;
    __shared__ float tile[18][18];
    __shared__ float k9[9];
    for (int i = t; i < 324; i += 256) ((float*)tile)[i] = 0.f;
    __syncthreads();
    int h = t >> 4, w = t & 15;
    size_t base = (size_t)m * 65536 + c * 256;
    tile[h + 1][w + 1] = fa[base + t];
    if (t < 9) k9[t] = kern[m * 2304 + c * 9 + t];
    __syncthreads();
    float s = 0.f;
#pragma unroll
    for (int di = 0; di < 3; di++)
#pragma unroll
        for (int dj = 0; dj < 3; dj++)
            s += k9[di * 3 + dj] * tile[h + di][w + dj];
    out[base + t] = s;
}

__global__ __launch_bounds__(256) void gn_kernel(
    const float* __restrict__ X, const float* __restrict__ gg,
    const float* __restrict__ gb, float* __restrict__ O)
{
    int g = blockIdx.x, m = blockIdx.y, t = threadIdx.x;
    size_t base = (size_t)m * 65536 + g * 2048;
    float4 v0 = *(const float4*)&X[base + t * 8];
    float4 v1 = *(const float4*)&X[base + t * 8 + 4];
    float s = v0.x + v0.y + v0.z + v0.w + v1.x + v1.y + v1.z + v1.w;
    float q = v0.x * v0.x + v0.y * v0.y + v0.z * v0.z + v0.w * v0.w +
              v1.x * v1.x + v1.y * v1.y + v1.z * v1.z + v1.w * v1.w;
    __shared__ float sS[8], sQ[8];
    __shared__ float mu_s, rs_s;
    s = warp_sum(s); q = warp_sum(q);
    int wid = t >> 5, lane = t & 31;
    if (lane == 0) { sS[wid] = s; sQ[wid] = q; }
    __syncthreads();
    if (t == 0) {
        float S = 0, Q = 0;
        for (int i = 0; i < 8; i++) { S += sS[i]; Q += sQ[i]; }
        float mu = S * (1.f / 2048.f);
        float var = Q * (1.f / 2048.f) - mu * mu;
        mu_s = mu; rs_s = rsqrtf(var + EPS_);
    }
    __syncthreads();
    float vals[8] = {v0.x, v0.y, v0.z, v0.w, v1.x, v1.y, v1.z, v1.w};
#pragma unroll
    for (int j = 0; j < 8; j++) {
        int local = t * 8 + j;
        int c = g * 8 + (local >> 8);
        O[base + local] = (vals[j] - mu_s) * rs_s * gg[c] + gb[c];
    }
}

// final per-sample stats from 8 conv-CTA partials per sample
__global__ __launch_bounds__(128) void zfin_kernel(
    const float* __restrict__ psum, const float* __restrict__ psq,
    float* __restrict__ muv, float* __restrict__ rsv)
{
    int m = threadIdx.x;
    float S = 0.f, Q = 0.f;
#pragma unroll
    for (int i = 0; i < 8; i++) { S += psum[m * 8 + i]; Q += psq[m * 8 + i]; }
    float mu = S * (1.f / 65536.f);
    float var = Q * (1.f / 65536.f) - mu * mu;
    muv[m] = mu;
    rsv[m] = rsqrtf(var + EPS_);
}

__global__ __launch_bounds__(256) void final_kernel(
    const float* __restrict__ z, const float* __restrict__ mu, const float* __restrict__ rs,
    const float* __restrict__ dg, const float* __restrict__ db, float* __restrict__ out)
{
    int i4 = blockIdx.x * 256 + threadIdx.x;
    int idx = i4 * 4;
    int m = idx >> 16, j = idx & 65535;
    float4 zv = *(const float4*)&z[idx];
    float4 gv = *(const float4*)&dg[j];
    float4 bv = *(const float4*)&db[j];
    float mm = mu[m], rr = rs[m];
    float4 o;
    o.x = (zv.x - mm) * rr * gv.x + bv.x;
    o.y = (zv.y - mm) * rr * gv.y + bv.y;
    o.z = (zv.z - mm) * rr * gv.z + bv.z;
    o.w = (zv.w - mm) * rr * gv.w + bv.w;
    *(float4*)&out[idx] = o;
}

// ===========================================================================
extern "C" void kernel_launch(void* const* d_in, const int* in_sizes, int n_in,
                              void* d_out, int out_size)
{
    const float* feat = (const float*)d_in[0];
    const float* Wp   = (const float*)d_in[1];
    const float* bp   = (const float*)d_in[2];
    const float* Wu   = (const float*)d_in[3];
    const float* bu   = (const float*)d_in[4];
    // d_in[5..8] = Wq,bq,Wk,bk -> dead (softmax over size-1 axis == 1)
    const float* Wv   = (const float*)d_in[9];
    const float* bv   = (const float*)d_in[10];
    const float* Wo   = (const float*)d_in[11];
    const float* bo   = (const float*)d_in[12];
    const float* ln1g = (const float*)d_in[13];
    const float* ln1b = (const float*)d_in[14];
    const float* Wk1  = (const float*)d_in[15];
    const float* bk1  = (const float*)d_in[16];
    const float* Wk2  = (const float*)d_in[17];
    const float* bk2  = (const float*)d_in[18];
    const float* Wpc  = (const float*)d_in[19];
    const float* bpc  = (const float*)d_in[20];
    const float* gng  = (const float*)d_in[21];
    const float* gnb  = (const float*)d_in[22];
    const float* Wf1  = (const float*)d_in[23];
    const float* bf1  = (const float*)d_in[24];
    const float* Wf2  = (const float*)d_in[25];
    const float* bf2  = (const float*)d_in[26];
    const float* dng  = (const float*)d_in[27];
    const float* dnb  = (const float*)d_in[28];
    float* out = (float*)d_out;

    void* sp_ = nullptr;
    cudaGetSymbolAddress(&sp_, g_scratch);
    float* s = (float*)sp_;
    float* ws   = s;                  // 2,097,152 (split-K partials)
    float* tp   = ws + 2097152;
    float* vv   = tp + 65536;         // (unused now, kept for layout)
    float* attn = vv + 65536;         // (unused now)
    float* enh  = attn + 65536;
    float* fa   = enh + 65536;
    float* b1   = fa + 8388608;
    float* b2   = b1 + 8388608;       // also Wo partial planes (4 x 65536)
    float* gapb = b2 + 8388608;
    float* hid  = gapb + 32768;       // (unused now)
    float* kern = hid + 32768;
    float* muv  = kern + 294912;
    float* rsv  = muv + 128;
    float* psum = rsv + 128;          // 1024
    float* psq  = psum + 1024;        // 1024

    static int smem_set = 0;
    if (!smem_set) {
        cudaFuncSetAttribute(mg_kernel<0, 0, 0, 0, 0>, cudaFuncAttributeMaxDynamicSharedMemorySize, MG_SMEM);
        cudaFuncSetAttribute(mg_kernel<1, 0, 0, 0, 0>, cudaFuncAttributeMaxDynamicSharedMemorySize, MG_SMEM);
        cudaFuncSetAttribute(mg_kernel<0, 0, 0, 1, 0>, cudaFuncAttributeMaxDynamicSharedMemorySize, MG_SMEM);
        cudaFuncSetAttribute(mg_kernel<0, 0, 1, 0, 0>, cudaFuncAttributeMaxDynamicSharedMemorySize, MG_SMEM);
        cudaFuncSetAttribute(mg_kernel<0, 0, 1, 2, 0>, cudaFuncAttributeMaxDynamicSharedMemorySize, MG_SMEM);
        cudaFuncSetAttribute(mg_kernel<0, 1, 1, 0, 0>, cudaFuncAttributeMaxDynamicSharedMemorySize, MG_SMEM);
        cudaFuncSetAttribute(mg_kernel<0, 1, 2, 0, 0>, cudaFuncAttributeMaxDynamicSharedMemorySize, MG_SMEM);
        cudaFuncSetAttribute(mg_kernel<0, 1, 3, 0, 1>, cudaFuncAttributeMaxDynamicSharedMemorySize, MG_SMEM);
        smem_set = 1;
    }

    // 1) tp = tokens @ Wp.T + bp   (split-K=32 -> deterministic reduce)
    mg_kernel<0, 0, 0, 0, 0><<<dim3(8, 1, 32), 256, MG_SMEM>>>(
        feat, Wp, nullptr, nullptr, ws, nullptr, nullptr, nullptr, 65536, 2048, 512, 65536, 0);
    spreduce_kernel<0><<<64, 256>>>(ws, bp, tp, 32, 65536, 511);
    // 2) Wv partials -> ws (4 planes); Wo reads (sum ws + bv) inline, partials -> b2
    mg_kernel<1, 0, 0, 0, 0><<<dim3(8, 1, 4), 256, MG_SMEM>>>(
        tp, Wv, nullptr, nullptr, ws, nullptr, nullptr, nullptr, 512, 128, 512, 512, 0);
    mg_kernel<0, 0, 0, 1, 0><<<dim3(8, 1, 4), 256, MG_SMEM>>>(
        ws, Wo, nullptr, nullptr, b2, bv, nullptr, nullptr, 512, 128, 512, 512, 65536);
    // 3) enh = LN((sum b2 planes + bo) + tp)   (fused attn reduce)
    ln1f_kernel<<<128, 512>>>(b2, bo, tp, ln1g, ln1b, enh);
    // 4) feat_attn = enh @ Wu.T + bu
    mg_kernel<0, 0, 1, 0, 0><<<dim3(1024, 1, 1), 256, MG_SMEM>>>(
        enh, Wu, bu, nullptr, fa, nullptr, nullptr, nullptr, 512, 512, 65536, 512, 0);
    // 5) gap; Wk1 partials -> ws (2 planes); Wk2 reads relu(sum + bk1) inline
    gap_kernel<<<128, 256>>>(fa, gapb);
    mg_kernel<0, 0, 0, 0, 0><<<dim3(4, 1, 2), 256, MG_SMEM>>>(
        gapb, Wk1, nullptr, nullptr, ws, nullptr, nullptr, nullptr, 256, 128, 256, 256, 0);
    mg_kernel<0, 0, 1, 2, 0><<<dim3(36, 1, 1), 256, MG_SMEM>>>(
        ws, Wk2, bk2, nullptr, kern, bk1, nullptr, nullptr, 256, 256, 2304, 256, 32768);
    // 6) depthwise 3x3
    dw_kernel<<<dim3(256, 128), 256>>>(fa, kern, b1);
    // 7) pointwise Wpc + bpc, then GroupNorm
    mg_kernel<0, 1, 1, 0, 0><<<dim3(512, 2, 1), 256, MG_SMEM>>>(
        Wpc, b1, bpc, nullptr, b2, nullptr, nullptr, nullptr, 256, 256, 0, 256, 0);
    gn_kernel<<<dim3(32, 128), 256>>>(b2, gng, gnb, b1);
    // 8) y = relu(conv Wf1); y = conv Wf2 + feat_attn (+ fused zstats partials)
    mg_kernel<0, 1, 2, 0, 0><<<dim3(512, 2, 1), 256, MG_SMEM>>>(
        Wf1, b1, bf1, nullptr, b2, nullptr, nullptr, nullptr, 256, 256, 0, 256, 0);
    mg_kernel<0, 1, 3, 0, 1><<<dim3(512, 2, 1), 256, MG_SMEM>>>(
        Wf2, b2, bf2, fa, b1, nullptr, psum, psq, 256, 256, 0, 256, 0);
    // 9) per-sample LayerNorm + affine (stats from fused partials)
    zfin_kernel<<<1, 128>>>(psum, psq, muv, rsv);
    final_kernel<<<8192, 256>>>(b1, muv, rsv, dng, dnb, out);
}

// round 15
// speedup vs baseline: 1.5037x; 1.5037x over previous
#include <cuda_runtime.h>
#include <cuda_bf16.h>
#include <cstdint>

#define EPS_ 1e-5f

// ---------------- scratch (single __device__ array) ----------------
__device__ float g_scratch[27885824];

__device__ __forceinline__ float warp_sum(float v) {
#pragma unroll
    for (int o = 16; o; o >>= 1) v += __shfl_down_sync(0xffffffffu, v, o);
    return v;
}

// split fp32 -> (hi bf16, lo bf16) pairs packed as bf16x2 words
__device__ __forceinline__ void cvt_split(float a, float b, uint32_t& hi, uint32_t& lo) {
    __nv_bfloat162 h = __floats2bfloat162_rn(a, b);
    float2 hf = __bfloat1622float2(h);
    __nv_bfloat162 l = __floats2bfloat162_rn(a - hf.x, b - hf.y);
    hi = *reinterpret_cast<uint32_t*>(&h);
    lo = *reinterpret_cast<uint32_t*>(&l);
}

__device__ __forceinline__ void mma16816(float* c, const uint32_t* a, const uint32_t* b) {
    asm volatile(
        "mma.sync.aligned.m16n8k16.row.col.f32.bf16.bf16.f32 "
        "{%0,%1,%2,%3}, {%4,%5,%6,%7}, {%8,%9}, {%0,%1,%2,%3};"
        : "+f"(c[0]), "+f"(c[1]), "+f"(c[2]), "+f"(c[3])
        : "r"(a[0]), "r"(a[1]), "r"(a[2]), "r"(a[3]), "r"(b[0]), "r"(b[1]));
}

__device__ __forceinline__ void ldsm4(uint32_t* r, uint32_t addr) {
    asm volatile(
        "ldmatrix.sync.aligned.m8n8.x4.shared.b16 {%0,%1,%2,%3}, [%4];"
        : "=r"(r[0]), "=r"(r[1]), "=r"(r[2]), "=r"(r[3]) : "r"(addr));
}

// ===========================================================================
// mma.sync GEMM, K-chunk 32, 2-stage smem double buffer + register prefetch.
// Quad-region smem layout (R9) + ldmatrix fragment loads (R10).
//  Per buffer: A hi/lo planes (4 quad-regions each, rows at stride 16B) then
//  B hi/lo planes. Region bases offset 0/8/16/24 mod 32 banks ->
//  conflict-free STS.128; one ldmatrix.x4 per fragment quad.
// Pipeline (1 barrier/chunk): at top of iter ch, buf[ch&1] holds chunk ch,
//  regs hold chunk ch+1 global data (loaded a full iteration earlier).
//  sync; store regs -> buf[1-(ch&1)]; issue LDG ch+2; compute chunk ch.
// C[m,n] = act( sum_k A[m,k]*B[n,k] (+bias) (+res) )
// Block 256 thr (8 warps, 4x2 of 32x32 warp tiles), tile M=128 x N=64,
// split-K = blockIdx.z. SHIFT: v_next row remap. BCONV: 1x1-conv B gather.
// EPI: 0=partial store (split-K), 1=bias, 2=bias+relu, 3=bias+residual.
// ===========================================================================
#define AQ0 0
#define AQ1 520
#define AQ2 1040
#define AQ3 1560
#define APLANE 2080          // A low plane base (word offset)
#define BQ0 0
#define BQ1 264
#define BQ2 528
#define BQ3 792
#define BH_BASE 4160
#define BL_BASE 5216
#define BUF_WORDS 6272
#define BUF_BYTES 25088
#define MG_SMEM (2 * BUF_BYTES)   // 50176 B -> dynamic smem, opt-in >48KB

template <int SHIFT, int BCONV, int EPI>
__global__ __launch_bounds__(256, 2) void mg_kernel(
    const float* __restrict__ A, const float* __restrict__ Bm,
    const float* __restrict__ bias, const float* __restrict__ res,
    float* __restrict__ C, int K, int kLen, int Ntot, int Astride)
{
    extern __shared__ __align__(128) uint32_t SM[];
    const int t = threadIdx.x, w = t >> 5, lid = t & 31;
    const int wm = (w >> 1) * 32, wn = (w & 1) * 32;
    const int t4 = lid & 3, grp = lid >> 2;
    const int n0 = blockIdx.x * 64;
    const int m0 = blockIdx.y * 128;
    const int sp = blockIdx.z;
    const int k0base = sp * kLen;
    const int nn = n0 >> 8, p0 = n0 & 255;  // BCONV decode

    float acc[2][4][4];
#pragma unroll
    for (int i = 0; i < 2; i++)
#pragma unroll
        for (int j = 0; j < 4; j++)
#pragma unroll
            for (int q = 0; q < 4; q++) acc[i][j][q] = 0.f;

    // ---- A global-load mapping: row = t>>1, 16 consecutive k at (t&1)*16 ----
    int am = m0 + (t >> 1);
    if (SHIFT) { int bb = am >> 5, ii = (am & 31) + 1; if (ii > 31) ii = 31; am = (bb << 5) + ii; }
    const float* Aptr = A + (size_t)am * Astride + k0base + (t & 1) * 16;
    const int ar4 = (t >> 1) * 4;
    const int ah_ = t & 1;
    const int iA0 = (ah_ ? AQ2 : AQ0) + ar4;
    const int iA1 = (ah_ ? AQ3 : AQ1) + ar4;

    // ---- B global-load mapping (threads 0..127) ----
    const int bactive = (t < 128);
    const int brow = BCONV ? (t & 63) : (t >> 1);
    const int bh_ = BCONV ? ((t >> 6) & 1) : (t & 1);
    const float* Bptr = BCONV
        ? Bm + (size_t)nn * 65536 + (size_t)(bh_ * 16) * 256 + p0 + brow
        : Bm + (size_t)(n0 + brow) * K + k0base + bh_ * 16;
    const int br4 = brow * 4;
    const int iB0 = BH_BASE + (bh_ ? BQ2 : BQ0) + br4;
    const int iB1 = BH_BASE + (bh_ ? BQ3 : BQ1) + br4;

    // ---- ldmatrix lane-address bases (bytes into buffer 0) ----
    const uint32_t smb = (uint32_t)__cvta_generic_to_shared(SM);
    const uint32_t baseA = smb + 4u * ((lid < 16 ? AQ0 : AQ1) + (uint32_t)(wm + (lid & 15)) * 4u);
    const uint32_t baseB = smb + 4u * ((uint32_t)BH_BASE + (((lid >> 3) & 1) ? BQ1 : BQ0)
                                       + (uint32_t)(wn + ((lid >> 4) << 3) + (lid & 7)) * 4u);

    const int nchunks = kLen >> 5;
    float apf[16], bpf[16];

    // ---- load chunk 0 into regs ----
    {
#pragma unroll
        for (int i = 0; i < 16; i += 4) {
            float4 v = *(const float4*)(Aptr + i);
            apf[i] = v.x; apf[i + 1] = v.y; apf[i + 2] = v.z; apf[i + 3] = v.w;
        }
        if (bactive) {
            if (!BCONV) {
#pragma unroll
                for (int i = 0; i < 16; i += 4) {
                    float4 v = *(const float4*)(Bptr + i);
                    bpf[i] = v.x; bpf[i + 1] = v.y; bpf[i + 2] = v.z; bpf[i + 3] = v.w;
                }
            } else {
#pragma unroll
                for (int i = 0; i < 16; i++) bpf[i] = Bptr[i * 256];
            }
        }
    }
    // ---- store chunk 0 to buffer 0 ----
    {
        uint32_t hw[8], lw[8];
#pragma unroll
        for (int i = 0; i < 16; i += 4) {
            cvt_split(apf[i], apf[i + 1], hw[i / 2], lw[i / 2]);
            cvt_split(apf[i + 2], apf[i + 3], hw[i / 2 + 1], lw[i / 2 + 1]);
        }
        *(uint4*)(SM + iA0)          = make_uint4(hw[0], hw[1], hw[2], hw[3]);
        *(uint4*)(SM + iA1)          = make_uint4(hw[4], hw[5], hw[6], hw[7]);
        *(uint4*)(SM + iA0 + APLANE) = make_uint4(lw[0], lw[1], lw[2], lw[3]);
        *(uint4*)(SM + iA1 + APLANE) = make_uint4(lw[4], lw[5], lw[6], lw[7]);
        if (bactive) {
            uint32_t bh[8], bl[8];
#pragma unroll
            for (int i = 0; i < 16; i += 4) {
                cvt_split(bpf[i], bpf[i + 1], bh[i / 2], bl[i / 2]);
                cvt_split(bpf[i + 2], bpf[i + 3], bh[i / 2 + 1], bl[i / 2 + 1]);
            }
            *(uint4*)(SM + iB0)                      = make_uint4(bh[0], bh[1], bh[2], bh[3]);
            *(uint4*)(SM + iB1)                      = make_uint4(bh[4], bh[5], bh[6], bh[7]);
            *(uint4*)(SM + iB0 + (BL_BASE - BH_BASE)) = make_uint4(bl[0], bl[1], bl[2], bl[3]);
            *(uint4*)(SM + iB1 + (BL_BASE - BH_BASE)) = make_uint4(bl[4], bl[5], bl[6], bl[7]);
        }
    }
    // ---- load chunk 1 into regs ----
    if (nchunks > 1) {
        const float* p = Aptr + 32;
#pragma unroll
        for (int i = 0; i < 16; i += 4) {
            float4 v = *(const float4*)(p + i);
            apf[i] = v.x; apf[i + 1] = v.y; apf[i + 2] = v.z; apf[i + 3] = v.w;
        }
        if (bactive) {
            if (!BCONV) {
                const float* q = Bptr + 32;
#pragma unroll
                for (int i = 0; i < 16; i += 4) {
                    float4 v = *(const float4*)(q + i);
                    bpf[i] = v.x; bpf[i + 1] = v.y; bpf[i + 2] = v.z; bpf[i + 3] = v.w;
                }
            } else {
                const float* q = Bptr + (size_t)32 * 256;
#pragma unroll
                for (int i = 0; i < 16; i++) bpf[i] = q[i * 256];
            }
        }
    }

    for (int ch = 0; ch < nchunks; ch++) {
        __syncthreads();
        // ---- store chunk ch+1 (in regs) to the other buffer ----
        if (ch + 1 < nchunks) {
            const int bw = ((ch + 1) & 1) * BUF_WORDS;
            uint32_t hw[8], lw[8];
#pragma unroll
            for (int i = 0; i < 16; i += 4) {
                cvt_split(apf[i], apf[i + 1], hw[i / 2], lw[i / 2]);
                cvt_split(apf[i + 2], apf[i + 3], hw[i / 2 + 1], lw[i / 2 + 1]);
            }
            *(uint4*)(SM + bw + iA0)          = make_uint4(hw[0], hw[1], hw[2], hw[3]);
            *(uint4*)(SM + bw + iA1)          = make_uint4(hw[4], hw[5], hw[6], hw[7]);
            *(uint4*)(SM + bw + iA0 + APLANE) = make_uint4(lw[0], lw[1], lw[2], lw[3]);
            *(uint4*)(SM + bw + iA1 + APLANE) = make_uint4(lw[4], lw[5], lw[6], lw[7]);
            if (bactive) {
                uint32_t bh[8], bl[8];
#pragma unroll
                for (int i = 0; i < 16; i += 4) {
                    cvt_split(bpf[i], bpf[i + 1], bh[i / 2], bl[i / 2]);
                    cvt_split(bpf[i + 2], bpf[i + 3], bh[i / 2 + 1], bl[i / 2 + 1]);
                }
                *(uint4*)(SM + bw + iB0)                      = make_uint4(bh[0], bh[1], bh[2], bh[3]);
                *(uint4*)(SM + bw + iB1)                      = make_uint4(bh[4], bh[5], bh[6], bh[7]);
                *(uint4*)(SM + bw + iB0 + (BL_BASE - BH_BASE)) = make_uint4(bl[0], bl[1], bl[2], bl[3]);
                *(uint4*)(SM + bw + iB1 + (BL_BASE - BH_BASE)) = make_uint4(bl[4], bl[5], bl[6], bl[7]);
            }
        }
        // ---- issue global loads for chunk ch+2 ----
        if (ch + 2 < nchunks) {
            const int kc = (ch + 2) << 5;
            const float* p = Aptr + kc;
#pragma unroll
            for (int i = 0; i < 16; i += 4) {
                float4 v = *(const float4*)(p + i);
                apf[i] = v.x; apf[i + 1] = v.y; apf[i + 2] = v.z; apf[i + 3] = v.w;
            }
            if (bactive) {
                if (!BCONV) {
                    const float* q = Bptr + kc;
#pragma unroll
                    for (int i = 0; i < 16; i += 4) {
                        float4 v = *(const float4*)(q + i);
                        bpf[i] = v.x; bpf[i + 1] = v.y; bpf[i + 2] = v.z; bpf[i + 3] = v.w;
                    }
                } else {
                    const float* q = Bptr + (size_t)kc * 256;
#pragma unroll
                    for (int i = 0; i < 16; i++) bpf[i] = q[i * 256];
                }
            }
        }
        // ---- compute chunk ch from buf[ch&1] (2 k16 steps, 3 split passes) ----
        const uint32_t bufb = (uint32_t)(ch & 1) * BUF_BYTES;
#pragma unroll
        for (int ks = 0; ks < 2; ks++) {
            const uint32_t aksoff = bufb + (uint32_t)ks * 4160u;
            const uint32_t bksoff = bufb + (uint32_t)ks * 2112u;
            uint32_t ah0[4], ah1[4], al0[4], al1[4], b0[4], b1[4];
            ldsm4(ah0, baseA + aksoff);
            ldsm4(ah1, baseA + aksoff + 256u);
            ldsm4(b0, baseB + bksoff);
            ldsm4(b1, baseB + bksoff + 256u);
            mma16816(acc[0][0], ah0, b0);     mma16816(acc[0][1], ah0, b0 + 2);
            mma16816(acc[0][2], ah0, b1);     mma16816(acc[0][3], ah0, b1 + 2);
            mma16816(acc[1][0], ah1, b0);     mma16816(acc[1][1], ah1, b0 + 2);
            mma16816(acc[1][2], ah1, b1);     mma16816(acc[1][3], ah1, b1 + 2);
            ldsm4(al0, baseA + aksoff + 8320u);
            ldsm4(al1, baseA + aksoff + 8320u + 256u);
            mma16816(acc[0][0], al0, b0);     mma16816(acc[0][1], al0, b0 + 2);
            mma16816(acc[0][2], al0, b1);     mma16816(acc[0][3], al0, b1 + 2);
            mma16816(acc[1][0], al1, b0);     mma16816(acc[1][1], al1, b0 + 2);
            mma16816(acc[1][2], al1, b1);     mma16816(acc[1][3], al1, b1 + 2);
            ldsm4(b0, baseB + bksoff + 4224u);
            ldsm4(b1, baseB + bksoff + 4224u + 256u);
            mma16816(acc[0][0], ah0, b0);     mma16816(acc[0][1], ah0, b0 + 2);
            mma16816(acc[0][2], ah0, b1);     mma16816(acc[0][3], ah0, b1 + 2);
            mma16816(acc[1][0], ah1, b0);     mma16816(acc[1][1], ah1, b0 + 2);
            mma16816(acc[1][2], ah1, b1);     mma16816(acc[1][3], ah1, b1 + 2);
        }
    }

    // ---- epilogue ----
#pragma unroll
    for (int mi = 0; mi < 2; mi++) {
        const int r0 = m0 + wm + mi * 16 + grp;
        const int r1 = r0 + 8;
        if (EPI == 0) {
            float* C0 = C + ((size_t)sp * 128 + r0) * Ntot + n0;
            float* C1 = C + ((size_t)sp * 128 + r1) * Ntot + n0;
#pragma unroll
            for (int ni = 0; ni < 4; ni++) {
                const int cw = wn + ni * 8 + 2 * t4;
                *(float2*)(C0 + cw) = make_float2(acc[mi][ni][0], acc[mi][ni][1]);
                *(float2*)(C1 + cw) = make_float2(acc[mi][ni][2], acc[mi][ni][3]);
            }
        } else if (!BCONV) {
            float* C0 = C + (size_t)r0 * Ntot;
            float* C1 = C + (size_t)r1 * Ntot;
#pragma unroll
            for (int ni = 0; ni < 4; ni++) {
                const int col = n0 + wn + ni * 8 + 2 * t4;
                float b0_ = bias[col], b1_ = bias[col + 1];
                float2 o0 = make_float2(acc[mi][ni][0] + b0_, acc[mi][ni][1] + b1_);
                float2 o1 = make_float2(acc[mi][ni][2] + b0_, acc[mi][ni][3] + b1_);
                if (EPI == 2) {
                    o0.x = fmaxf(o0.x, 0.f); o0.y = fmaxf(o0.y, 0.f);
                    o1.x = fmaxf(o1.x, 0.f); o1.y = fmaxf(o1.y, 0.f);
                }
                *(float2*)(C0 + col) = o0;
                *(float2*)(C1 + col) = o1;
            }
        } else {
            const float bm0 = bias[r0], bm1 = bias[r1];
            float* P0 = C + (size_t)nn * 65536 + (size_t)r0 * 256 + p0;
            float* P1 = C + (size_t)nn * 65536 + (size_t)r1 * 256 + p0;
            const float* R0 = (EPI == 3) ? res + (size_t)nn * 65536 + (size_t)r0 * 256 + p0 : nullptr;
            const float* R1 = (EPI == 3) ? res + (size_t)nn * 65536 + (size_t)r1 * 256 + p0 : nullptr;
#pragma unroll
            for (int ni = 0; ni < 4; ni++) {
                const int cw = wn + ni * 8 + 2 * t4;
                float2 o0 = make_float2(acc[mi][ni][0] + bm0, acc[mi][ni][1] + bm0);
                float2 o1 = make_float2(acc[mi][ni][2] + bm1, acc[mi][ni][3] + bm1);
                if (EPI == 2) {
                    o0.x = fmaxf(o0.x, 0.f); o0.y = fmaxf(o0.y, 0.f);
                    o1.x = fmaxf(o1.x, 0.f); o1.y = fmaxf(o1.y, 0.f);
                }
                if (EPI == 3) {
                    float2 q0 = *(const float2*)(R0 + cw);
                    float2 q1 = *(const float2*)(R1 + cw);
                    o0.x += q0.x; o0.y += q0.y; o1.x += q1.x; o1.y += q1.y;
                }
                *(float2*)(P0 + cw) = o0;
                *(float2*)(P1 + cw) = o1;
            }
        }
    }
}

// ===================== split-K reduce, float4 (+bias, optional relu) =====================
template <int RELU>
__global__ __launch_bounds__(256) void spreduce_kernel(
    const float* __restrict__ ws, const float* __restrict__ bias,
    float* __restrict__ out, int nsp, int Nel, int NtotMask)
{
    int idx = (blockIdx.x * 256 + threadIdx.x) * 4;
    if (idx >= Nel) return;
    float4 s = *(const float4*)&bias[idx & NtotMask];
    for (int sp = 0; sp < nsp; sp++) {
        float4 v = *(const float4*)&ws[(size_t)sp * Nel + idx];
        s.x += v.x; s.y += v.y; s.z += v.z; s.w += v.w;
    }
    if (RELU) {
        s.x = fmaxf(s.x, 0.f); s.y = fmaxf(s.y, 0.f);
        s.z = fmaxf(s.z, 0.f); s.w = fmaxf(s.w, 0.f);
    }
    *(float4*)&out[idx] = s;
}

// ===================== SIMT kernels (mem-bound) =====================
// ln1 fused with attn split-K reduce: attn = bo + sum_sp planes; x = attn + tp
__global__ __launch_bounds__(512) void ln1f_kernel(
    const float* __restrict__ planes, const float* __restrict__ bo,
    const float* __restrict__ tp,
    const float* __restrict__ g, const float* __restrict__ b, float* __restrict__ enh)
{
    int m = blockIdx.x, t = threadIdx.x;
    int idx = m * 512 + t;
    float a = bo[t];
#pragma unroll
    for (int sp = 0; sp < 4; sp++) a += planes[sp * 65536 + idx];
    float x = a + tp[idx];
    __shared__ float sS[16], sQ[16];
    __shared__ float mu_s, rs_s;
    float s = warp_sum(x), q = warp_sum(x * x);
    int wid = t >> 5, lane = t & 31;
    if (lane == 0) { sS[wid] = s; sQ[wid] = q; }
    __syncthreads();
    if (t == 0) {
        float S = 0, Q = 0;
        for (int i = 0; i < 16; i++) { S += sS[i]; Q += sQ[i]; }
        float mu = S * (1.f / 512.f);
        float var = Q * (1.f / 512.f) - mu * mu;
        mu_s = mu; rs_s = rsqrtf(var + EPS_);
    }
    __syncthreads();
    enh[idx] = (x - mu_s) * rs_s * g[t] + b[t];
}

__global__ __launch_bounds__(256) void gap_kernel(
    const float* __restrict__ fa, float* __restrict__ gap)
{
    int m = blockIdx.x, t = threadIdx.x;
    int wid = t >> 5, lane = t & 31;
    for (int it = 0; it < 32; it++) {
        int c = wid * 32 + it;
        const float* p = fa + (size_t)m * 65536 + c * 256 + lane * 8;
        float4 a = *(const float4*)p;
        float4 b = *(const float4*)(p + 4);
        float s = a.x + a.y + a.z + a.w + b.x + b.y + b.z + b.w;
        s = warp_sum(s);
        if (lane == 0) gap[m * 256 + c] = s * (1.f / 256.f);
    }
}

__global__ __launch_bounds__(256) void dw_kernel(
    const float* __restrict__ fa, const float* __restrict__ kern, float* __restrict__ out)
{
    int c = blockIdx.x, m = blockIdx.y, t = threadIdx.x;
    __shared__ float tile[18][18];
    __shared__ float k9[9];
    for (int i = t; i < 324; i += 256) ((float*)tile)[i] = 0.f;
    __syncthreads();
    int h = t >> 4, w = t & 15;
    size_t base = (size_t)m * 65536 + c * 256;
    tile[h + 1][w + 1] = fa[base + t];
    if (t < 9) k9[t] = kern[m * 2304 + c * 9 + t];
    __syncthreads();
    float s = 0.f;
#pragma unroll
    for (int di = 0; di < 3; di++)
#pragma unroll
        for (int dj = 0; dj < 3; dj++)
            s += k9[di * 3 + dj] * tile[h + di][w + dj];
    out[base + t] = s;
}

__global__ __launch_bounds__(256) void gn_kernel(
    const float* __restrict__ X, const float* __restrict__ gg,
    const float* __restrict__ gb, float* __restrict__ O)
{
    int g = blockIdx.x, m = blockIdx.y, t = threadIdx.x;
    size_t base = (size_t)m * 65536 + g * 2048;
    float4 v0 = *(const float4*)&X[base + t * 8];
    float4 v1 = *(const float4*)&X[base + t * 8 + 4];
    float s = v0.x + v0.y + v0.z + v0.w + v1.x + v1.y + v1.z + v1.w;
    float q = v0.x * v0.x + v0.y * v0.y + v0.z * v0.z + v0.w * v0.w +
              v1.x * v1.x + v1.y * v1.y + v1.z * v1.z + v1.w * v1.w;
    __shared__ float sS[8], sQ[8];
    __shared__ float mu_s, rs_s;
    s = warp_sum(s); q = warp_sum(q);
    int wid = t >> 5, lane = t & 31;
    if (lane == 0) { sS[wid] = s; sQ[wid] = q; }
    __syncthreads();
    if (t == 0) {
        float S = 0, Q = 0;
        for (int i = 0; i < 8; i++) { S += sS[i]; Q += sQ[i]; }
        float mu = S * (1.f / 2048.f);
        float var = Q * (1.f / 2048.f) - mu * mu;
        mu_s = mu; rs_s = rsqrtf(var + EPS_);
    }
    __syncthreads();
    float vals[8] = {v0.x, v0.y, v0.z, v0.w, v1.x, v1.y, v1.z, v1.w};
#pragma unroll
    for (int j = 0; j < 8; j++) {
        int local = t * 8 + j;
        int c = g * 8 + (local >> 8);
        O[base + local] = (vals[j] - mu_s) * rs_s * gg[c] + gb[c];
    }
}

__global__ __launch_bounds__(256) void zstats_kernel(
    const float* __restrict__ z, float* __restrict__ mu_out, float* __restrict__ rs_out)
{
    int m = blockIdx.x, t = threadIdx.x;
    const float* row = z + (size_t)m * 65536;
    float s = 0.f, q = 0.f;
    for (int i = t * 4; i < 65536; i += 1024) {
        float4 v = *(const float4*)&row[i];
        s += v.x + v.y + v.z + v.w;
        q += v.x * v.x + v.y * v.y + v.z * v.z + v.w * v.w;
    }
    __shared__ float sS[8], sQ[8];
    s = warp_sum(s); q = warp_sum(q);
    int wid = t >> 5, lane = t & 31;
    if (lane == 0) { sS[wid] = s; sQ[wid] = q; }
    __syncthreads();
    if (t == 0) {
        float S = 0, Q = 0;
        for (int i = 0; i < 8; i++) { S += sS[i]; Q += sQ[i]; }
        float mu = S * (1.f / 65536.f);
        float var = Q * (1.f / 65536.f) - mu * mu;
        mu_out[m] = mu;
        rs_out[m] = rsqrtf(var + EPS_);
    }
}

__global__ __launch_bounds__(256) void final_kernel(
    const float* __restrict__ z, const float* __restrict__ mu, const float* __restrict__ rs,
    const float* __restrict__ dg, const float* __restrict__ db, float* __restrict__ out)
{
    int i4 = blockIdx.x * 256 + threadIdx.x;
    int idx = i4 * 4;
    int m = idx >> 16, j = idx & 65535;
    float4 zv = *(const float4*)&z[idx];
    float4 gv = *(const float4*)&dg[j];
    float4 bv = *(const float4*)&db[j];
    float mm = mu[m], rr = rs[m];
    float4 o;
    o.x = (zv.x - mm) * rr * gv.x + bv.x;
    o.y = (zv.y - mm) * rr * gv.y + bv.y;
    o.z = (zv.z - mm) * rr * gv.z + bv.z;
    o.w = (zv.w - mm) * rr * gv.w + bv.w;
    *(float4*)&out[idx] = o;
}

// ===========================================================================
extern "C" void kernel_launch(void* const* d_in, const int* in_sizes, int n_in,
                              void* d_out, int out_size)
{
    const float* feat = (const float*)d_in[0];
    const float* Wp   = (const float*)d_in[1];
    const float* bp   = (const float*)d_in[2];
    const float* Wu   = (const float*)d_in[3];
    const float* bu   = (const float*)d_in[4];
    // d_in[5..8] = Wq,bq,Wk,bk -> dead (softmax over size-1 axis == 1)
    const float* Wv   = (const float*)d_in[9];
    const float* bv   = (const float*)d_in[10];
    const float* Wo   = (const float*)d_in[11];
    const float* bo   = (const float*)d_in[12];
    const float* ln1g = (const float*)d_in[13];
    const float* ln1b = (const float*)d_in[14];
    const float* Wk1  = (const float*)d_in[15];
    const float* bk1  = (const float*)d_in[16];
    const float* Wk2  = (const float*)d_in[17];
    const float* bk2  = (const float*)d_in[18];
    const float* Wpc  = (const float*)d_in[19];
    const float* bpc  = (const float*)d_in[20];
    const float* gng  = (const float*)d_in[21];
    const float* gnb  = (const float*)d_in[22];
    const float* Wf1  = (const float*)d_in[23];
    const float* bf1  = (const float*)d_in[24];
    const float* Wf2  = (const float*)d_in[25];
    const float* bf2  = (const float*)d_in[26];
    const float* dng  = (const float*)d_in[27];
    const float* dnb  = (const float*)d_in[28];
    float* out = (float*)d_out;

    void* sp_ = nullptr;
    cudaGetSymbolAddress(&sp_, g_scratch);
    float* s = (float*)sp_;
    float* ws   = s;
    float* tp   = ws + 2097152;
    float* vv   = tp + 65536;
    float* attn = vv + 65536;
    float* enh  = attn + 65536;
    float* fa   = enh + 65536;
    float* b1   = fa + 8388608;
    float* b2   = b1 + 8388608;
    float* gapb = b2 + 8388608;
    float* hid  = gapb + 32768;
    float* kern = hid + 32768;
    float* muv  = kern + 294912;
    float* rsv  = muv + 128;

    // opt-in >48KB dynamic smem (host-side, capture-safe; proven in R5)
    static int smem_set = 0;
    if (!smem_set) {
        cudaFuncSetAttribute(mg_kernel<0, 0, 0>, cudaFuncAttributeMaxDynamicSharedMemorySize, MG_SMEM);
        cudaFuncSetAttribute(mg_kernel<1, 0, 0>, cudaFuncAttributeMaxDynamicSharedMemorySize, MG_SMEM);
        cudaFuncSetAttribute(mg_kernel<0, 0, 1>, cudaFuncAttributeMaxDynamicSharedMemorySize, MG_SMEM);
        cudaFuncSetAttribute(mg_kernel<0, 1, 1>, cudaFuncAttributeMaxDynamicSharedMemorySize, MG_SMEM);
        cudaFuncSetAttribute(mg_kernel<0, 1, 2>, cudaFuncAttributeMaxDynamicSharedMemorySize, MG_SMEM);
        cudaFuncSetAttribute(mg_kernel<0, 1, 3>, cudaFuncAttributeMaxDynamicSharedMemorySize, MG_SMEM);
        smem_set = 1;
    }

    // 1) tp = tokens @ Wp.T + bp   (split-K=32 -> deterministic reduce)
    mg_kernel<0, 0, 0><<<dim3(8, 1, 32), 256, MG_SMEM>>>(feat, Wp, nullptr, nullptr, ws, 65536, 2048, 512, 65536);
    spreduce_kernel<0><<<64, 256>>>(ws, bp, tp, 32, 65536, 511);
    // 2) vv = v_next @ Wv.T + bv ; Wo partials -> b2 (4 planes), reduce fused in ln1f
    mg_kernel<1, 0, 0><<<dim3(8, 1, 4), 256, MG_SMEM>>>(tp, Wv, nullptr, nullptr, ws, 512, 128, 512, 512);
    spreduce_kernel<0><<<64, 256>>>(ws, bv, vv, 4, 65536, 511);
    mg_kernel<0, 0, 0><<<dim3(8, 1, 4), 256, MG_SMEM>>>(vv, Wo, nullptr, nullptr, b2, 512, 128, 512, 512);
    // 3) enh = LN((sum b2 planes + bo) + tp)   (fused attn reduce)
    ln1f_kernel<<<128, 512>>>(b2, bo, tp, ln1g, ln1b, enh);
    // 4) feat_attn = enh @ Wu.T + bu
    mg_kernel<0, 0, 1><<<dim3(1024, 1, 1), 256, MG_SMEM>>>(enh, Wu, bu, nullptr, fa, 512, 512, 65536, 512);
    // 5) gap -> hid -> kern
    gap_kernel<<<128, 256>>>(fa, gapb);
    mg_kernel<0, 0, 0><<<dim3(4, 1, 2), 256, MG_SMEM>>>(gapb, Wk1, nullptr, nullptr, ws, 256, 128, 256, 256);
    spreduce_kernel<1><<<32, 256>>>(ws, bk1, hid, 2, 32768, 255);
    mg_kernel<0, 0, 1><<<dim3(36, 1, 1), 256, MG_SMEM>>>(hid, Wk2, bk2, nullptr, kern, 256, 256, 2304, 256);
    // 6) depthwise 3x3
    dw_kernel<<<dim3(256, 128), 256>>>(fa, kern, b1);
    // 7) pointwise Wpc + bpc, then GroupNorm
    mg_kernel<0, 1, 1><<<dim3(512, 2, 1), 256, MG_SMEM>>>(Wpc, b1, bpc, nullptr, b2, 256, 256, 0, 256);
    gn_kernel<<<dim3(32, 128), 256>>>(b2, gng, gnb, b1);
    // 8) y = relu(conv Wf1); y = conv Wf2 + feat_attn
    mg_kernel<0, 1, 2><<<dim3(512, 2, 1), 256, MG_SMEM>>>(Wf1, b1, bf1, nullptr, b2, 256, 256, 0, 256);
    mg_kernel<0, 1, 3><<<dim3(512, 2, 1), 256, MG_SMEM>>>(Wf2, b2, bf2, fa, b1, 256, 256, 0, 256);
    // 9) per-sample LayerNorm + affine
    zstats_kernel<<<128, 256>>>(b1, muv, rsv);
    final_kernel<<<8192, 256>>>(b1, muv, rsv, dng, dnb, out);
}

// round 17
// speedup vs baseline: 1.5417x; 1.0253x over previous
#include <cuda_runtime.h>
#include <cuda_bf16.h>
#include <cstdint>

#define EPS_ 1e-5f

// ---------------- scratch (single __device__ array) ----------------
__device__ float g_scratch[27885824];

__device__ __forceinline__ float warp_sum(float v) {
#pragma unroll
    for (int o = 16; o; o >>= 1) v += __shfl_down_sync(0xffffffffu, v, o);
    return v;
}

// split fp32 -> (hi bf16, lo bf16) pairs packed as bf16x2 words
__device__ __forceinline__ void cvt_split(float a, float b, uint32_t& hi, uint32_t& lo) {
    __nv_bfloat162 h = __floats2bfloat162_rn(a, b);
    float2 hf = __bfloat1622float2(h);
    __nv_bfloat162 l = __floats2bfloat162_rn(a - hf.x, b - hf.y);
    hi = *reinterpret_cast<uint32_t*>(&h);
    lo = *reinterpret_cast<uint32_t*>(&l);
}

__device__ __forceinline__ void mma16816(float* c, const uint32_t* a, const uint32_t* b) {
    asm volatile(
        "mma.sync.aligned.m16n8k16.row.col.f32.bf16.bf16.f32 "
        "{%0,%1,%2,%3}, {%4,%5,%6,%7}, {%8,%9}, {%0,%1,%2,%3};"
        : "+f"(c[0]), "+f"(c[1]), "+f"(c[2]), "+f"(c[3])
        : "r"(a[0]), "r"(a[1]), "r"(a[2]), "r"(a[3]), "r"(b[0]), "r"(b[1]));
}

__device__ __forceinline__ void ldsm4(uint32_t* r, uint32_t addr) {
    asm volatile(
        "ldmatrix.sync.aligned.m8n8.x4.shared.b16 {%0,%1,%2,%3}, [%4];"
        : "=r"(r[0]), "=r"(r[1]), "=r"(r[2]), "=r"(r[3]) : "r"(addr));
}

// ===========================================================================
// mma.sync GEMM, K-chunk 32, 2-stage smem double buffer + register prefetch.
// CTA tile 128(M) x 128(N), warp tile 32x64 (8 warps, 4x2).
// Quad-region smem layout + ldmatrix fragment loads.
//  A and B planes have identical geometry: 128 rows, 4 quad-regions per
//  plane (one per 8-k subblock), row r = 4 consecutive u32 words at r*4.
//  Region bases offset 0/8/16/24 mod 32 banks -> conflict-free STS.128.
// Pipeline (1 barrier/chunk): buf[ch&1] holds chunk ch; regs hold ch+1.
//  sync; store regs -> buf[1-(ch&1)]; issue LDG ch+2; compute chunk ch.
// C[m,n] = act( sum_k A[m,k]*B[n,k] (+bias) (+res) )
// split-K = blockIdx.z. SHIFT: v_next row remap. BCONV: 1x1-conv B gather
// (column block = 128 px of one sample).
// EPI: 0=partial store (split-K), 1=bias, 2=bias+relu, 3=bias+residual.
// ===========================================================================
#define AQ0 0
#define AQ1 520
#define AQ2 1040
#define AQ3 1560
#define APLANE 2080          // lo plane offset (words), same for A and B
#define BH_BASE 4160         // B hi plane base (words)
#define BUF_WORDS 8320
#define BUF_BYTES 33280
#define MG_SMEM (2 * BUF_BYTES)   // 66560 B -> dynamic smem, opt-in >48KB

template <int SHIFT, int BCONV, int EPI>
__global__ __launch_bounds__(256) void mg_kernel(
    const float* __restrict__ A, const float* __restrict__ Bm,
    const float* __restrict__ bias, const float* __restrict__ res,
    float* __restrict__ C, int K, int kLen, int Ntot, int Astride)
{
    extern __shared__ __align__(128) uint32_t SM[];
    const int t = threadIdx.x, w = t >> 5, lid = t & 31;
    const int wm = (w >> 1) * 32, wn = (w & 1) * 64;
    const int t4 = lid & 3, grp = lid >> 2;
    const int n0 = blockIdx.x * 128;
    const int m0 = blockIdx.y * 128;
    const int sp = blockIdx.z;
    const int k0base = sp * kLen;
    const int nn = n0 >> 8, p0 = n0 & 255;  // BCONV decode (128-px block)

    float acc[2][8][4];
#pragma unroll
    for (int i = 0; i < 2; i++)
#pragma unroll
        for (int j = 0; j < 8; j++)
#pragma unroll
            for (int q = 0; q < 4; q++) acc[i][j][q] = 0.f;

    // ---- A global-load mapping: row = t>>1, 16 consecutive k at (t&1)*16 ----
    int am = m0 + (t >> 1);
    if (SHIFT) { int bb = am >> 5, ii = (am & 31) + 1; if (ii > 31) ii = 31; am = (bb << 5) + ii; }
    const float* Aptr = A + (size_t)am * Astride + k0base + (t & 1) * 16;
    const int ar4 = (t >> 1) * 4;
    const int ah_ = t & 1;
    const int iA0 = (ah_ ? AQ2 : AQ0) + ar4;
    const int iA1 = (ah_ ? AQ3 : AQ1) + ar4;

    // ---- B global-load mapping (all 256 threads; 128 rows x 2 halves) ----
    const int brow = BCONV ? (t & 127) : (t >> 1);
    const int bh_ = BCONV ? (t >> 7) : (t & 1);
    const float* Bptr = BCONV
        ? Bm + (size_t)nn * 65536 + (size_t)(bh_ * 16) * 256 + p0 + brow
        : Bm + (size_t)(n0 + brow) * K + k0base + bh_ * 16;
    const int br4 = brow * 4;
    const int iB0 = BH_BASE + (bh_ ? AQ2 : AQ0) + br4;
    const int iB1 = BH_BASE + (bh_ ? AQ3 : AQ1) + br4;

    // ---- ldmatrix lane-address bases (bytes into buffer 0) ----
    const uint32_t smb = (uint32_t)__cvta_generic_to_shared(SM);
    const uint32_t baseA = smb + 4u * ((lid < 16 ? AQ0 : AQ1) + (uint32_t)(wm + (lid & 15)) * 4u);
    const uint32_t baseB = smb + 4u * ((uint32_t)BH_BASE + (((lid >> 3) & 1) ? AQ1 : AQ0)
                                       + (uint32_t)(wn + ((lid >> 4) << 3) + (lid & 7)) * 4u);

    const int nchunks = kLen >> 5;
    float apf[16], bpf[16];

#define MG_LOADA(KC)                                                        \
    {                                                                       \
        const float* p_ = Aptr + (KC);                                      \
        _Pragma("unroll")                                                   \
        for (int i = 0; i < 16; i += 4) {                                   \
            float4 v = *(const float4*)(p_ + i);                            \
            apf[i] = v.x; apf[i+1] = v.y; apf[i+2] = v.z; apf[i+3] = v.w;   \
        }                                                                   \
    }
#define MG_LOADB(KC)                                                        \
    if (!BCONV) {                                                           \
        const float* q_ = Bptr + (KC);                                      \
        _Pragma("unroll")                                                   \
        for (int i = 0; i < 16; i += 4) {                                   \
            float4 v = *(const float4*)(q_ + i);                            \
            bpf[i] = v.x; bpf[i+1] = v.y; bpf[i+2] = v.z; bpf[i+3] = v.w;   \
        }                                                                   \
    } else {                                                                \
        const float* q_ = Bptr + (size_t)(KC) * 256;                        \
        _Pragma("unroll")                                                   \
        for (int i = 0; i < 16; i++) bpf[i] = q_[i * 256];                  \
    }
#define MG_STORE(BW)                                                        \
    {                                                                       \
        uint32_t hw[8], lw[8];                                              \
        _Pragma("unroll")                                                   \
        for (int i = 0; i < 16; i += 4) {                                   \
            cvt_split(apf[i], apf[i+1], hw[i/2], lw[i/2]);                  \
            cvt_split(apf[i+2], apf[i+3], hw[i/2+1], lw[i/2+1]);            \
        }                                                                   \
        *(uint4*)(SM + (BW) + iA0)          = make_uint4(hw[0], hw[1], hw[2], hw[3]); \
        *(uint4*)(SM + (BW) + iA1)          = make_uint4(hw[4], hw[5], hw[6], hw[7]); \
        *(uint4*)(SM + (BW) + iA0 + APLANE) = make_uint4(lw[0], lw[1], lw[2], lw[3]); \
        *(uint4*)(SM + (BW) + iA1 + APLANE) = make_uint4(lw[4], lw[5], lw[6], lw[7]); \
        _Pragma("unroll")                                                   \
        for (int i = 0; i < 16; i += 4) {                                   \
            cvt_split(bpf[i], bpf[i+1], hw[i/2], lw[i/2]);                  \
            cvt_split(bpf[i+2], bpf[i+3], hw[i/2+1], lw[i/2+1]);            \
        }                                                                   \
        *(uint4*)(SM + (BW) + iB0)          = make_uint4(hw[0], hw[1], hw[2], hw[3]); \
        *(uint4*)(SM + (BW) + iB1)          = make_uint4(hw[4], hw[5], hw[6], hw[7]); \
        *(uint4*)(SM + (BW) + iB0 + APLANE) = make_uint4(lw[0], lw[1], lw[2], lw[3]); \
        *(uint4*)(SM + (BW) + iB1 + APLANE) = make_uint4(lw[4], lw[5], lw[6], lw[7]); \
    }

    // ---- prologue: chunk 0 -> buf0; chunk 1 -> regs ----
    MG_LOADA(0)
    MG_LOADB(0)
    MG_STORE(0)
    if (nchunks > 1) {
        MG_LOADA(32)
        MG_LOADB(32)
    }

    for (int ch = 0; ch < nchunks; ch++) {
        __syncthreads();
        if (ch + 1 < nchunks) {
            const int bw = ((ch + 1) & 1) * BUF_WORDS;
            MG_STORE(bw)
        }
        if (ch + 2 < nchunks) {
            const int kc = (ch + 2) << 5;
            MG_LOADA(kc)
            MG_LOADB(kc)
        }
        // ---- compute chunk ch from buf[ch&1] (2 k16 steps, 3 split passes) ----
        const uint32_t bufb = (uint32_t)(ch & 1) * BUF_BYTES;
#pragma unroll
        for (int ks = 0; ks < 2; ks++) {
            const uint32_t aks = bufb + (uint32_t)ks * 4160u;
            const uint32_t bks = bufb + (uint32_t)ks * 4160u;
            uint32_t ah0[4], ah1[4], al0[4], al1[4];
            uint32_t bb0[4], bb1[4], bb2[4], bb3[4];
            ldsm4(ah0, baseA + aks);
            ldsm4(ah1, baseA + aks + 256u);
            ldsm4(bb0, baseB + bks);
            ldsm4(bb1, baseB + bks + 256u);
            ldsm4(bb2, baseB + bks + 512u);
            ldsm4(bb3, baseB + bks + 768u);
            // pass 1: ah * bh
            mma16816(acc[0][0], ah0, bb0); mma16816(acc[0][1], ah0, bb0 + 2);
            mma16816(acc[0][2], ah0, bb1); mma16816(acc[0][3], ah0, bb1 + 2);
            mma16816(acc[0][4], ah0, bb2); mma16816(acc[0][5], ah0, bb2 + 2);
            mma16816(acc[0][6], ah0, bb3); mma16816(acc[0][7], ah0, bb3 + 2);
            mma16816(acc[1][0], ah1, bb0); mma16816(acc[1][1], ah1, bb0 + 2);
            mma16816(acc[1][2], ah1, bb1); mma16816(acc[1][3], ah1, bb1 + 2);
            mma16816(acc[1][4], ah1, bb2); mma16816(acc[1][5], ah1, bb2 + 2);
            mma16816(acc[1][6], ah1, bb3); mma16816(acc[1][7], ah1, bb3 + 2);
            // pass 2: al * bh
            ldsm4(al0, baseA + aks + 8320u);
            ldsm4(al1, baseA + aks + 8320u + 256u);
            mma16816(acc[0][0], al0, bb0); mma16816(acc[0][1], al0, bb0 + 2);
            mma16816(acc[0][2], al0, bb1); mma16816(acc[0][3], al0, bb1 + 2);
            mma16816(acc[0][4], al0, bb2); mma16816(acc[0][5], al0, bb2 + 2);
            mma16816(acc[0][6], al0, bb3); mma16816(acc[0][7], al0, bb3 + 2);
            mma16816(acc[1][0], al1, bb0); mma16816(acc[1][1], al1, bb0 + 2);
            mma16816(acc[1][2], al1, bb1); mma16816(acc[1][3], al1, bb1 + 2);
            mma16816(acc[1][4], al1, bb2); mma16816(acc[1][5], al1, bb2 + 2);
            mma16816(acc[1][6], al1, bb3); mma16816(acc[1][7], al1, bb3 + 2);
            // pass 3: ah * bl
            ldsm4(bb0, baseB + bks + 8320u);
            ldsm4(bb1, baseB + bks + 8320u + 256u);
            ldsm4(bb2, baseB + bks + 8320u + 512u);
            ldsm4(bb3, baseB + bks + 8320u + 768u);
            mma16816(acc[0][0], ah0, bb0); mma16816(acc[0][1], ah0, bb0 + 2);
            mma16816(acc[0][2], ah0, bb1); mma16816(acc[0][3], ah0, bb1 + 2);
            mma16816(acc[0][4], ah0, bb2); mma16816(acc[0][5], ah0, bb2 + 2);
            mma16816(acc[0][6], ah0, bb3); mma16816(acc[0][7], ah0, bb3 + 2);
            mma16816(acc[1][0], ah1, bb0); mma16816(acc[1][1], ah1, bb0 + 2);
            mma16816(acc[1][2], ah1, bb1); mma16816(acc[1][3], ah1, bb1 + 2);
            mma16816(acc[1][4], ah1, bb2); mma16816(acc[1][5], ah1, bb2 + 2);
            mma16816(acc[1][6], ah1, bb3); mma16816(acc[1][7], ah1, bb3 + 2);
        }
    }
#undef MG_LOADA
#undef MG_LOADB
#undef MG_STORE

    // ---- epilogue ----
#pragma unroll
    for (int mi = 0; mi < 2; mi++) {
        const int r0 = m0 + wm + mi * 16 + grp;
        const int r1 = r0 + 8;
        if (EPI == 0) {
            float* C0 = C + ((size_t)sp * 128 + r0) * Ntot + n0;
            float* C1 = C + ((size_t)sp * 128 + r1) * Ntot + n0;
#pragma unroll
            for (int ni = 0; ni < 8; ni++) {
                const int cw = wn + ni * 8 + 2 * t4;
                *(float2*)(C0 + cw) = make_float2(acc[mi][ni][0], acc[mi][ni][1]);
                *(float2*)(C1 + cw) = make_float2(acc[mi][ni][2], acc[mi][ni][3]);
            }
        } else if (!BCONV) {
            float* C0 = C + (size_t)r0 * Ntot;
            float* C1 = C + (size_t)r1 * Ntot;
#pragma unroll
            for (int ni = 0; ni < 8; ni++) {
                const int col = n0 + wn + ni * 8 + 2 * t4;
                float b0_ = bias[col], b1_ = bias[col + 1];
                float2 o0 = make_float2(acc[mi][ni][0] + b0_, acc[mi][ni][1] + b1_);
                float2 o1 = make_float2(acc[mi][ni][2] + b0_, acc[mi][ni][3] + b1_);
                if (EPI == 2) {
                    o0.x = fmaxf(o0.x, 0.f); o0.y = fmaxf(o0.y, 0.f);
                    o1.x = fmaxf(o1.x, 0.f); o1.y = fmaxf(o1.y, 0.f);
                }
                *(float2*)(C0 + col) = o0;
                *(float2*)(C1 + col) = o1;
            }
        } else {
            const float bm0 = bias[r0], bm1 = bias[r1];
            float* P0 = C + (size_t)nn * 65536 + (size_t)r0 * 256 + p0;
            float* P1 = C + (size_t)nn * 65536 + (size_t)r1 * 256 + p0;
            const float* R0 = (EPI == 3) ? res + (size_t)nn * 65536 + (size_t)r0 * 256 + p0 : nullptr;
            const float* R1 = (EPI == 3) ? res + (size_t)nn * 65536 + (size_t)r1 * 256 + p0 : nullptr;
#pragma unroll
            for (int ni = 0; ni < 8; ni++) {
                const int cw = wn + ni * 8 + 2 * t4;
                float2 o0 = make_float2(acc[mi][ni][0] + bm0, acc[mi][ni][1] + bm0);
                float2 o1 = make_float2(acc[mi][ni][2] + bm1, acc[mi][ni][3] + bm1);
                if (EPI == 2) {
                    o0.x = fmaxf(o0.x, 0.f); o0.y = fmaxf(o0.y, 0.f);
                    o1.x = fmaxf(o1.x, 0.f); o1.y = fmaxf(o1.y, 0.f);
                }
                if (EPI == 3) {
                    float2 q0 = *(const float2*)(R0 + cw);
                    float2 q1 = *(const float2*)(R1 + cw);
                    o0.x += q0.x; o0.y += q0.y; o1.x += q1.x; o1.y += q1.y;
                }
                *(float2*)(P0 + cw) = o0;
                *(float2*)(P1 + cw) = o1;
            }
        }
    }
}

// ===================== split-K reduce, float4 (+bias, optional relu) =====================
template <int RELU>
__global__ __launch_bounds__(256) void spreduce_kernel(
    const float* __restrict__ ws, const float* __restrict__ bias,
    float* __restrict__ out, int nsp, int Nel, int NtotMask)
{
    int idx = (blockIdx.x * 256 + threadIdx.x) * 4;
    if (idx >= Nel) return;
    float4 s = *(const float4*)&bias[idx & NtotMask];
    for (int sp = 0; sp < nsp; sp++) {
        float4 v = *(const float4*)&ws[(size_t)sp * Nel + idx];
        s.x += v.x; s.y += v.y; s.z += v.z; s.w += v.w;
    }
    if (RELU) {
        s.x = fmaxf(s.x, 0.f); s.y = fmaxf(s.y, 0.f);
        s.z = fmaxf(s.z, 0.f); s.w = fmaxf(s.w, 0.f);
    }
    *(float4*)&out[idx] = s;
}

// ===================== SIMT kernels (mem-bound) =====================
// ln1 fused with attn split-K reduce: attn = bo + sum_sp planes; x = attn + tp
__global__ __launch_bounds__(512) void ln1f_kernel(
    const float* __restrict__ planes, const float* __restrict__ bo,
    const float* __restrict__ tp,
    const float* __restrict__ g, const float* __restrict__ b, float* __restrict__ enh)
{
    int m = blockIdx.x, t = threadIdx.x;
    int idx = m * 512 + t;
    float a = bo[t];
#pragma unroll
    for (int sp = 0; sp < 4; sp++) a += planes[sp * 65536 + idx];
    float x = a + tp[idx];
    __shared__ float sS[16], sQ[16];
    __shared__ float mu_s, rs_s;
    float s = warp_sum(x), q = warp_sum(x * x);
    int wid = t >> 5, lane = t & 31;
    if (lane == 0) { sS[wid] = s; sQ[wid] = q; }
    __syncthreads();
    if (t == 0) {
        float S = 0, Q = 0;
        for (int i = 0; i < 16; i++) { S += sS[i]; Q += sQ[i]; }
        float mu = S * (1.f / 512.f);
        float var = Q * (1.f / 512.f) - mu * mu;
        mu_s = mu; rs_s = rsqrtf(var + EPS_);
    }
    __syncthreads();
    enh[idx] = (x - mu_s) * rs_s * g[t] + b[t];
}

__global__ __launch_bounds__(256) void gap_kernel(
    const float* __restrict__ fa, float* __restrict__ gap)
{
    int m = blockIdx.x, t = threadIdx.x;
    int wid = t >> 5, lane = t & 31;
    for (int it = 0; it < 32; it++) {
        int c = wid * 32 + it;
        const float* p = fa + (size_t)m * 65536 + c * 256 + lane * 8;
        float4 a = *(const float4*)p;
        float4 b = *(const float4*)(p + 4);
        float s = a.x + a.y + a.z + a.w + b.x + b.y + b.z + b.w;
        s = warp_sum(s);
        if (lane == 0) gap[m * 256 + c] = s * (1.f / 256.f);
    }
}

__global__ __launch_bounds__(256) void dw_kernel(
    const float* __restrict__ fa, const float* __restrict__ kern, float* __restrict__ out)
{
    int c = blockIdx.x, m = blockIdx.y, t = threadIdx.x;
    __shared__ float tile[18][18];
    __shared__ float k9[9];
    for (int i = t; i < 324; i += 256) ((float*)tile)[i] = 0.f;
    __syncthreads();
    int h = t >> 4, w = t & 15;
    size_t base = (size_t)m * 65536 + c * 256;
    tile[h + 1][w + 1] = fa[base + t];
    if (t < 9) k9[t] = kern[m * 2304 + c * 9 + t];
    __syncthreads();
    float s = 0.f;
#pragma unroll
    for (int di = 0; di < 3; di++)
#pragma unroll
        for (int dj = 0; dj < 3; dj++)
            s += k9[di * 3 + dj] * tile[h + di][w + dj];
    out[base + t] = s;
}

__global__ __launch_bounds__(256) void gn_kernel(
    const float* __restrict__ X, const float* __restrict__ gg,
    const float* __restrict__ gb, float* __restrict__ O)
{
    int g = blockIdx.x, m = blockIdx.y, t = threadIdx.x;
    size_t base = (size_t)m * 65536 + g * 2048;
    float4 v0 = *(const float4*)&X[base + t * 8];
    float4 v1 = *(const float4*)&X[base + t * 8 + 4];
    float s = v0.x + v0.y + v0.z + v0.w + v1.x + v1.y + v1.z + v1.w;
    float q = v0.x * v0.x + v0.y * v0.y + v0.z * v0.z + v0.w * v0.w +
              v1.x * v1.x + v1.y * v1.y + v1.z * v1.z + v1.w * v1.w;
    __shared__ float sS[8], sQ[8];
    __shared__ float mu_s, rs_s;
    s = warp_sum(s); q = warp_sum(q);
    int wid = t >> 5, lane = t & 31;
    if (lane == 0) { sS[wid] = s; sQ[wid] = q; }
    __syncthreads();
    if (t == 0) {
        float S = 0, Q = 0;
        for (int i = 0; i < 8; i++) { S += sS[i]; Q += sQ[i]; }
        float mu = S * (1.f / 2048.f);
        float var = Q * (1.f / 2048.f) - mu * mu;
        mu_s = mu; rs_s = rsqrtf(var + EPS_);
    }
    __syncthreads();
    float vals[8] = {v0.x, v0.y, v0.z, v0.w, v1.x, v1.y, v1.z, v1.w};
#pragma unroll
    for (int j = 0; j < 8; j++) {
        int local = t * 8 + j;
        int c = g * 8 + (local >> 8);
        O[base + local] = (vals[j] - mu_s) * rs_s * gg[c] + gb[c];
    }
}

__global__ __launch_bounds__(256) void zstats_kernel(
    const float* __restrict__ z, float* __restrict__ mu_out, float* __restrict__ rs_out)
{
    int m = blockIdx.x, t = threadIdx.x;
    const float* row = z + (size_t)m * 65536;
    float s = 0.f, q = 0.f;
    for (int i = t * 4; i < 65536; i += 1024) {
        float4 v = *(const float4*)&row[i];
        s += v.x + v.y + v.z + v.w;
        q += v.x * v.x + v.y * v.y + v.z * v.z + v.w * v.w;
    }
    __shared__ float sS[8], sQ[8];
    s = warp_sum(s); q = warp_sum(q);
    int wid = t >> 5, lane = t & 31;
    if (lane == 0) { sS[wid] = s; sQ[wid] = q; }
    __syncthreads();
    if (t == 0) {
        float S = 0, Q = 0;
        for (int i = 0; i < 8; i++) { S += sS[i]; Q += sQ[i]; }
        float mu = S * (1.f / 65536.f);
        float var = Q * (1.f / 65536.f) - mu * mu;
        mu_out[m] = mu;
        rs_out[m] = rsqrtf(var + EPS_);
    }
}

__global__ __launch_bounds__(256) void final_kernel(
    const float* __restrict__ z, const float* __restrict__ mu, const float* __restrict__ rs,
    const float* __restrict__ dg, const float* __restrict__ db, float* __restrict__ out)
{
    int i4 = blockIdx.x * 256 + threadIdx.x;
    int idx = i4 * 4;
    int m = idx >> 16, j = idx & 65535;
    float4 zv = *(const float4*)&z[idx];
    float4 gv = *(const float4*)&dg[j];
    float4 bv = *(const float4*)&db[j];
    float mm = mu[m], rr = rs[m];
    float4 o;
    o.x = (zv.x - mm) * rr * gv.x + bv.x;
    o.y = (zv.y - mm) * rr * gv.y + bv.y;
    o.z = (zv.z - mm) * rr * gv.z + bv.z;
    o.w = (zv.w - mm) * rr * gv.w + bv.w;
    *(float4*)&out[idx] = o;
}

// ===========================================================================
extern "C" void kernel_launch(void* const* d_in, const int* in_sizes, int n_in,
                              void* d_out, int out_size)
{
    const float* feat = (const float*)d_in[0];
    const float* Wp   = (const float*)d_in[1];
    const float* bp   = (const float*)d_in[2];
    const float* Wu   = (const float*)d_in[3];
    const float* bu   = (const float*)d_in[4];
    // d_in[5..8] = Wq,bq,Wk,bk -> dead (softmax over size-1 axis == 1)
    const float* Wv   = (const float*)d_in[9];
    const float* bv   = (const float*)d_in[10];
    const float* Wo   = (const float*)d_in[11];
    const float* bo   = (const float*)d_in[12];
    const float* ln1g = (const float*)d_in[13];
    const float* ln1b = (const float*)d_in[14];
    const float* Wk1  = (const float*)d_in[15];
    const float* bk1  = (const float*)d_in[16];
    const float* Wk2  = (const float*)d_in[17];
    const float* bk2  = (const float*)d_in[18];
    const float* Wpc  = (const float*)d_in[19];
    const float* bpc  = (const float*)d_in[20];
    const float* gng  = (const float*)d_in[21];
    const float* gnb  = (const float*)d_in[22];
    const float* Wf1  = (const float*)d_in[23];
    const float* bf1  = (const float*)d_in[24];
    const float* Wf2  = (const float*)d_in[25];
    const float* bf2  = (const float*)d_in[26];
    const float* dng  = (const float*)d_in[27];
    const float* dnb  = (const float*)d_in[28];
    float* out = (float*)d_out;

    void* sp_ = nullptr;
    cudaGetSymbolAddress(&sp_, g_scratch);
    float* s = (float*)sp_;
    float* ws   = s;
    float* tp   = ws + 2097152;
    float* vv   = tp + 65536;
    float* attn = vv + 65536;
    float* enh  = attn + 65536;
    float* fa   = enh + 65536;
    float* b1   = fa + 8388608;
    float* b2   = b1 + 8388608;
    float* gapb = b2 + 8388608;
    float* hid  = gapb + 32768;
    float* kern = hid + 32768;
    float* muv  = kern + 294912;
    float* rsv  = muv + 128;

    // opt-in >48KB dynamic smem (host-side, capture-safe; proven in R5)
    static int smem_set = 0;
    if (!smem_set) {
        cudaFuncSetAttribute(mg_kernel<0, 0, 0>, cudaFuncAttributeMaxDynamicSharedMemorySize, MG_SMEM);
        cudaFuncSetAttribute(mg_kernel<1, 0, 0>, cudaFuncAttributeMaxDynamicSharedMemorySize, MG_SMEM);
        cudaFuncSetAttribute(mg_kernel<0, 0, 1>, cudaFuncAttributeMaxDynamicSharedMemorySize, MG_SMEM);
        cudaFuncSetAttribute(mg_kernel<0, 1, 1>, cudaFuncAttributeMaxDynamicSharedMemorySize, MG_SMEM);
        cudaFuncSetAttribute(mg_kernel<0, 1, 2>, cudaFuncAttributeMaxDynamicSharedMemorySize, MG_SMEM);
        cudaFuncSetAttribute(mg_kernel<0, 1, 3>, cudaFuncAttributeMaxDynamicSharedMemorySize, MG_SMEM);
        smem_set = 1;
    }

    // 1) tp = tokens @ Wp.T + bp   (split-K=32 -> deterministic reduce)
    mg_kernel<0, 0, 0><<<dim3(4, 1, 32), 256, MG_SMEM>>>(feat, Wp, nullptr, nullptr, ws, 65536, 2048, 512, 65536);
    spreduce_kernel<0><<<64, 256>>>(ws, bp, tp, 32, 65536, 511);
    // 2) vv = v_next @ Wv.T + bv ; Wo partials -> b2 (4 planes), reduce fused in ln1f
    mg_kernel<1, 0, 0><<<dim3(4, 1, 4), 256, MG_SMEM>>>(tp, Wv, nullptr, nullptr, ws, 512, 128, 512, 512);
    spreduce_kernel<0><<<64, 256>>>(ws, bv, vv, 4, 65536, 511);
    mg_kernel<0, 0, 0><<<dim3(4, 1, 4), 256, MG_SMEM>>>(vv, Wo, nullptr, nullptr, b2, 512, 128, 512, 512);
    // 3) enh = LN((sum b2 planes + bo) + tp)   (fused attn reduce)
    ln1f_kernel<<<128, 512>>>(b2, bo, tp, ln1g, ln1b, enh);
    // 4) feat_attn = enh @ Wu.T + bu
    mg_kernel<0, 0, 1><<<dim3(512, 1, 1), 256, MG_SMEM>>>(enh, Wu, bu, nullptr, fa, 512, 512, 65536, 512);
    // 5) gap -> hid -> kern
    gap_kernel<<<128, 256>>>(fa, gapb);
    mg_kernel<0, 0, 0><<<dim3(2, 1, 2), 256, MG_SMEM>>>(gapb, Wk1, nullptr, nullptr, ws, 256, 128, 256, 256);
    spreduce_kernel<1><<<32, 256>>>(ws, bk1, hid, 2, 32768, 255);
    mg_kernel<0, 0, 1><<<dim3(18, 1, 1), 256, MG_SMEM>>>(hid, Wk2, bk2, nullptr, kern, 256, 256, 2304, 256);
    // 6) depthwise 3x3
    dw_kernel<<<dim3(256, 128), 256>>>(fa, kern, b1);
    // 7) pointwise Wpc + bpc, then GroupNorm
    mg_kernel<0, 1, 1><<<dim3(256, 2, 1), 256, MG_SMEM>>>(Wpc, b1, bpc, nullptr, b2, 256, 256, 0, 256);
    gn_kernel<<<dim3(32, 128), 256>>>(b2, gng, gnb, b1);
    // 8) y = relu(conv Wf1); y = conv Wf2 + feat_attn
    mg_kernel<0, 1, 2><<<dim3(256, 2, 1), 256, MG_SMEM>>>(Wf1, b1, bf1, nullptr, b2, 256, 256, 0, 256);
    mg_kernel<0, 1, 3><<<dim3(256, 2, 1), 256, MG_SMEM>>>(Wf2, b2, bf2, fa, b1, 256, 256, 0, 256);
    // 9) per-sample LayerNorm + affine
    zstats_kernel<<<128, 256>>>(b1, muv, rsv);
    final_kernel<<<8192, 256>>>(b1, muv, rsv, dng, dnb, out);
}